// round 14
// baseline (speedup 1.0000x reference)
#include <cuda_runtime.h>
#include <cuda_fp16.h>
#include <cstdint>

#define B_   32
#define C_   128
#define CO_  96
#define H_   64
#define W_   64
#define HW_  4096
#define HP_  66
#define WP_  66
#define KTOT 1152   // 9 taps * 128 ci

// ---------------- device scratch (no allocations allowed) ----------------
__device__ __align__(16) __half g_xp[(size_t)B_ * HP_ * WP_ * C_]; // padded NHWC fp16
__device__ __align__(16) __half g_w[CO_ * KTOT];                   // A: [co][tap*128+ci]
__device__ int    g_idx[3 * C_];
__device__ __align__(16) __half g_medh[(size_t)B_ * C_ * HW_];     // median result, fp16 NCHW
__device__ float2 g_part[C_ * 8];
__device__ float2 g_sb[C_];

// ---------------- PTX helpers (sm_80-era: safe for compute_103) ----------------
__device__ __forceinline__ uint32_t smem_u32(const void* p) {
    uint32_t a;
    asm("{ .reg .u64 t; cvta.to.shared.u64 t, %1; cvt.u32.u64 %0, t; }" : "=r"(a) : "l"(p));
    return a;
}
__device__ __forceinline__ void ldsm4(uint32_t* r, uint32_t addr) {
    asm volatile("ldmatrix.sync.aligned.m8n8.x4.shared.b16 {%0,%1,%2,%3}, [%4];"
        : "=r"(r[0]), "=r"(r[1]), "=r"(r[2]), "=r"(r[3]) : "r"(addr));
}
// full-rate fp16-accumulate HMMA
__device__ __forceinline__ void mma16816_h(uint32_t* d, const uint32_t* a, const uint32_t* b) {
    asm volatile("mma.sync.aligned.m16n8k16.row.col.f16.f16.f16.f16 "
        "{%0,%1}, {%2,%3,%4,%5}, {%6,%7}, {%0,%1};"
        : "+r"(d[0]), "+r"(d[1])
        : "r"(a[0]), "r"(a[1]), "r"(a[2]), "r"(a[3]), "r"(b[0]), "r"(b[1]));
}

// SMEM layout (halves): sB halo [132][72] then sA [3][96][72]
#define SB_HALVES (132 * 72)   // 9504 halves = 19008 B
#define TILE_A    (96 * 72)    // 6912 halves = 13824 B
#define DSM_HALVES (SB_HALVES + 3 * TILE_A)   // 30240 halves = 60480 B

// ---------------- 1) one-hot indices from hs ----------------
__global__ void idx_kernel(const float* __restrict__ hs) {
    int t = blockIdx.x * blockDim.x + threadIdx.x;
    if (t >= 3 * C_) return;
    int j = t >> 7, c = t & 127;
    int d = 0;
    for (int dd = 0; dd < 32; ++dd)
        if (hs[(j * 32 + dd) * C_ + c] > 0.5f) d = dd;
    g_idx[t] = d;
}

// ---------------- 2) sketched weights -> fp16, [co][tap*128+ci] ----------------
__global__ void wsk_kernel(const float* __restrict__ w2, const float* __restrict__ ss) {
    int e = blockIdx.x * 256 + threadIdx.x;
    if (e >= CO_ * KTOT) return;
    int ci = e & 127, tap = (e >> 7) % 9, co = e / KTOT;
    int j = co >> 5, d = co & 31;
    float sum = 0.f;
    for (int c = 0; c < C_; ++c) {
        int   ic = g_idx[j * C_ + c];
        float wv = w2[(c * C_ + ci) * 9 + tap];
        sum += (ic == d) ? ss[j * C_ + c] * wv : 0.f;
    }
    g_w[e] = __float2half_rn(sum);
}

// ---------------- 3a) zero padded borders of g_xp ----------------
__global__ void zero_kernel() {
    int t = blockIdx.x * 256 + threadIdx.x;          // B_ * 260 * 16
    if (t >= B_ * 260 * 16) return;
    int v  = t & 15;
    int pb = (t >> 4) % 260;
    int b  = t / (260 * 16);
    int h, w;
    if (pb < 66)       { h = 0;  w = pb; }
    else if (pb < 132) { h = 65; w = pb - 66; }
    else { int q = pb - 132; h = 1 + (q >> 1); w = (q & 1) * 65; }
    size_t off = (((size_t)b * HP_ + h) * WP_ + w) * C_ + v * 8;
    *(uint4*)(g_xp + off) = make_uint4(0, 0, 0, 0);
}

// ---------------- 3b) NCHW fp32 -> padded NHWC fp16 ----------------
__global__ __launch_bounds__(256) void xT_kernel(const float* __restrict__ x) {
    __shared__ float sm[128 * 65];
    const int t = threadIdx.x, h = blockIdx.x, b = blockIdx.y;
    const float* xp = x + (size_t)b * C_ * HW_ + h * W_;
#pragma unroll
    for (int k = 0; k < 32; ++k) {
        int idx = (k << 8) + t;
        int c = idx >> 6, w = idx & 63;
        sm[c * 65 + w] = xp[(size_t)c * HW_ + w];
    }
    __syncthreads();
    size_t dbase = (((size_t)b * HP_ + h + 1) * WP_ + 1) * C_;
#pragma unroll
    for (int k = 0; k < 16; ++k) {
        int idx = (k << 8) + t;
        int w = idx >> 6, c2 = idx & 63;
        float f0 = sm[(2 * c2) * 65 + w];
        float f1 = sm[(2 * c2 + 1) * 65 + w];
        __half2 hh = __floats2half2_rn(f0, f1);
        size_t o = dbase + (size_t)w * C_ + 2 * c2;
        *(unsigned*)(g_xp + o) = *(unsigned*)&hh;
    }
}

// ---------------- 4) mma.sync conv, f16 accum (chain=4) folded to f32 per kw ----------------
__global__ __launch_bounds__(256, 2)
void conv_mma_kernel(const float* __restrict__ ss) {
    extern __shared__ __half dsm[];
    __half* sB = dsm;                  // halo: 132 pixel-rows x 72 (64 used)
    __half* sA = dsm + SB_HALVES;      // 3 kw tiles x 96 rows x 72

    const int tid = threadIdx.x, warp = tid >> 5, lane = tid & 31;
    const int b = blockIdx.y, h0 = blockIdx.x << 1;   // 2 output rows per CTA
    const int m0 = (warp >> 2) * 48;                  // 2 warps in M: 48 rows each
    const int n0 = (warp & 3) * 32;                   // 4 warps in N: 32 pixels each

    const uint32_t aB = smem_u32(sB), aA = smem_u32(sA);

    // ldmatrix per-lane offsets
    uint32_t a_off[3];
#pragma unroll
    for (int ti = 0; ti < 3; ++ti)
        a_off[ti] = (uint32_t)((m0 + ti * 16 + (lane & 15)) * 144 + (lane >> 4) * 16);
    uint32_t b_off[2];
    {
        int o = lane >> 3;
#pragma unroll
        for (int u = 0; u < 2; ++u) {
            int pix  = n0 + u * 16 + (o >> 1) * 8 + (lane & 7);
            int hrow = (pix >> 6) * 66 + (pix & 63);       // halo row (2 x 66 layout)
            b_off[u] = (uint32_t)(hrow * 144 + (o & 1) * 16);
        }
    }

    float acc[3][4][4];
#pragma unroll
    for (int ti = 0; ti < 3; ++ti)
#pragma unroll
        for (int tj = 0; tj < 4; ++tj)
#pragma unroll
            for (int v = 0; v < 4; ++v) acc[ti][tj][v] = 0.f;

#pragma unroll 1
    for (int it = 0; it < 6; ++it) {
        const int kh = it >> 1, half = it & 1;
        __syncthreads();
        // stage B halo: 132 rows (2 x 66 cols) x 64 ci = 1056 uint4
        const __half* xb = g_xp + (((size_t)b * HP_ + h0 + kh) * WP_) * C_ + half * 64;
#pragma unroll
        for (int k = 0; k < 5; ++k) {
            int g = tid + (k << 8);
            if (g < 1056) {
                int row = g >> 3, sub = g & 7;
                int r = (row >= 66) ? 1 : 0;
                int wn = row - r * 66;
                *(uint4*)(sB + row * 72 + sub * 8) =
                    *(const uint4*)(xb + ((size_t)r * WP_ + wn) * C_ + sub * 8);
            }
        }
        // stage A: 3 kw tiles, 96 rows x 64 ci each = 2304 uint4 (9 per thread)
        const __half* wb = g_w + (kh * 3) * 128 + half * 64;
#pragma unroll
        for (int k = 0; k < 9; ++k) {
            int g = tid + (k << 8);
            int tl = g / 768, rem = g - tl * 768;
            int row = rem >> 3, sub = rem & 7;
            *(uint4*)(sA + tl * TILE_A + row * 72 + sub * 8) =
                *(const uint4*)(wb + (size_t)row * KTOT + tl * 128 + sub * 8);
        }
        __syncthreads();

#pragma unroll
        for (int kw = 0; kw < 3; ++kw) {
            uint32_t acc16[3][4][2];
#pragma unroll
            for (int ti = 0; ti < 3; ++ti)
#pragma unroll
                for (int tj = 0; tj < 4; ++tj)
                    acc16[ti][tj][0] = acc16[ti][tj][1] = 0u;   // +0.0h pairs
#pragma unroll
            for (int s = 0; s < 4; ++s) {
                uint32_t a[3][4], bb2[8];
#pragma unroll
                for (int ti = 0; ti < 3; ++ti)
                    ldsm4(a[ti], aA + kw * 13824 + a_off[ti] + s * 32);
#pragma unroll
                for (int u = 0; u < 2; ++u)
                    ldsm4(&bb2[u * 4], aB + b_off[u] + kw * 144 + s * 32);
#pragma unroll
                for (int ti = 0; ti < 3; ++ti)
#pragma unroll
                    for (int tj = 0; tj < 4; ++tj)
                        mma16816_h(acc16[ti][tj], a[ti], &bb2[tj * 2]);
            }
            // fold f16 chain (K=64) into fp32 master accumulators
#pragma unroll
            for (int ti = 0; ti < 3; ++ti)
#pragma unroll
                for (int tj = 0; tj < 4; ++tj) {
                    float2 p0 = __half22float2(*(const __half2*)&acc16[ti][tj][0]);
                    float2 p1 = __half22float2(*(const __half2*)&acc16[ti][tj][1]);
                    acc[ti][tj][0] += p0.x;
                    acc[ti][tj][1] += p0.y;
                    acc[ti][tj][2] += p1.x;
                    acc[ti][tj][3] += p1.y;
                }
        }
    }

    // ---- accumulators -> SMEM yt[96][132] (reuse staging smem) ----
    __syncthreads();
    float* yt = (float*)dsm;
#pragma unroll
    for (int ti = 0; ti < 3; ++ti)
#pragma unroll
        for (int tj = 0; tj < 4; ++tj) {
            int row = m0 + ti * 16 + (lane >> 2);
            int col = n0 + tj * 8 + (lane & 3) * 2;
            *(float2*)&yt[row * 132 + col]       = make_float2(acc[ti][tj][0], acc[ti][tj][1]);
            *(float2*)&yt[(row + 8) * 132 + col] = make_float2(acc[ti][tj][2], acc[ti][tj][3]);
        }
    __syncthreads();

    // ---- unsketch (gather + sign) + median-of-3, fp16 coalesced store ----
    const int sp = tid & 127, cg = tid >> 7;
    const int hh = h0 + (sp >> 6), wn = sp & 63;
    __half* mbase = g_medh + ((size_t)b * C_) * HW_ + hh * W_ + wn;
#pragma unroll 1
    for (int cc = 0; cc < 64; ++cc) {
        int c = (cg << 6) + cc;
        int i0 = g_idx[c], i1 = g_idx[C_ + c], i2 = g_idx[2 * C_ + c];
        float s0 = ss[c], s1 = ss[C_ + c], s2 = ss[2 * C_ + c];
        float v0 = s0 * yt[i0 * 132 + sp];
        float v1 = s1 * yt[(32 + i1) * 132 + sp];
        float v2 = s2 * yt[(64 + i2) * 132 + sp];
        float mx = fmaxf(v0, v1), mn = fminf(v0, v1);
        mbase[(size_t)c * HW_] = __float2half_rn(fmaxf(mn, fminf(mx, v2)));
    }
}

// ---------------- 5) BN stats (fp16 med), two-stage ----------------
__global__ void stats1_kernel() {
    const int c = blockIdx.x, q = blockIdx.y, tid = threadIdx.x;
    float s = 0.f, qq = 0.f;
    for (int bb = q * 4; bb < q * 4 + 4; ++bb) {
        const uint4* p = (const uint4*)(g_medh + ((size_t)bb * C_ + c) * HW_);
        for (int i = tid; i < HW_ / 8; i += 256) {
            uint4 v = p[i];
            const uint32_t wrd[4] = {v.x, v.y, v.z, v.w};
#pragma unroll
            for (int u = 0; u < 4; ++u) {
                float2 f = __half22float2(*(const __half2*)&wrd[u]);
                s += f.x + f.y;
                qq = fmaf(f.x, f.x, fmaf(f.y, f.y, qq));
            }
        }
    }
    __shared__ float rs[8], rq[8];
#pragma unroll
    for (int o = 16; o; o >>= 1) {
        s  += __shfl_down_sync(0xffffffffu, s,  o);
        qq += __shfl_down_sync(0xffffffffu, qq, o);
    }
    if ((tid & 31) == 0) { rs[tid >> 5] = s; rq[tid >> 5] = qq; }
    __syncthreads();
    if (tid == 0) {
        float S = 0.f, Q = 0.f;
        for (int i = 0; i < 8; ++i) { S += rs[i]; Q += rq[i]; }
        g_part[c * 8 + q] = make_float2(S, Q);
    }
}
__global__ void stats2_kernel(const float* __restrict__ gamma2,
                              const float* __restrict__ beta2) {
    int c = threadIdx.x;
    float S = 0.f, Q = 0.f;
    for (int q = 0; q < 8; ++q) { float2 p = g_part[c * 8 + q]; S += p.x; Q += p.y; }
    const float invn = 1.f / (float)(B_ * HW_);
    float mean  = S * invn;
    float var   = Q * invn - mean * mean;
    float scale = gamma2[c] * rsqrtf(var + 1e-5f);
    g_sb[c] = make_float2(scale, beta2[c] - mean * scale);
}

// ---------------- 6) normalize + ReLU + residual ----------------
__global__ void out_kernel(const float* __restrict__ x, float* __restrict__ out) {
    size_t i = ((size_t)blockIdx.x * 256 + threadIdx.x) << 2;
    int c = (int)((i >> 12) & 127);
    float2 sb = g_sb[c];
    uint2 mh = *(const uint2*)&g_medh[i];
    float2 f01 = __half22float2(*(const __half2*)&mh.x);
    float2 f23 = __half22float2(*(const __half2*)&mh.y);
    float4 xv = *(const float4*)&x[i];
    float4 o;
    o.x = fmaxf(fmaf(f01.x, sb.x, sb.y), 0.f) + xv.x;
    o.y = fmaxf(fmaf(f01.y, sb.x, sb.y), 0.f) + xv.y;
    o.z = fmaxf(fmaf(f23.x, sb.x, sb.y), 0.f) + xv.z;
    o.w = fmaxf(fmaf(f23.y, sb.x, sb.y), 0.f) + xv.w;
    *(float4*)&out[i] = o;
}

// ---------------- launch ----------------
extern "C" void kernel_launch(void* const* d_in, const int* in_sizes, int n_in,
                              void* d_out, int out_size) {
    (void)in_sizes; (void)n_in; (void)out_size;
    const float* x      = (const float*)d_in[0];
    // d_in[1] = w1, d_in[3] = gamma1, d_in[4] = beta1: unused (reference discards out1)
    const float* w2     = (const float*)d_in[2];
    const float* gamma2 = (const float*)d_in[5];
    const float* beta2  = (const float*)d_in[6];
    const float* hs     = (const float*)d_in[7];
    const float* ss     = (const float*)d_in[8];
    float* out = (float*)d_out;

    const int DSMEM = DSM_HALVES * 2;   // 60480 B (epilogue yt 50688 B fits)
    cudaFuncSetAttribute(conv_mma_kernel, cudaFuncAttributeMaxDynamicSharedMemorySize, DSMEM);

    idx_kernel<<<2, 256>>>(hs);
    wsk_kernel<<<(CO_ * KTOT + 255) / 256, 256>>>(w2, ss);
    zero_kernel<<<(B_ * 260 * 16 + 255) / 256, 256>>>();
    xT_kernel<<<dim3(H_, B_), 256>>>(x);
    conv_mma_kernel<<<dim3(H_ / 2, B_), 256, DSMEM>>>(ss);
    stats1_kernel<<<dim3(C_, 8), 256>>>();
    stats2_kernel<<<1, C_>>>(gamma2, beta2);
    out_kernel<<<(B_ * C_ * HW_) / 1024, 256>>>(x, out);
}

// round 15
// speedup vs baseline: 1.0064x; 1.0064x over previous
#include <cuda_runtime.h>
#include <cuda_fp16.h>
#include <cstdint>

#define B_   32
#define C_   128
#define CO_  96
#define H_   64
#define W_   64
#define HW_  4096
#define HP_  66
#define WP_  66
#define KTOT 1152   // 9 taps * 128 ci

// ---------------- device scratch (no allocations allowed) ----------------
__device__ __align__(16) __half g_xp[(size_t)B_ * HP_ * WP_ * C_]; // padded NHWC fp16
__device__ __align__(16) __half g_w[CO_ * KTOT];                   // A: [co][tap*128+ci]
__device__ int    g_idx[3 * C_];
__device__ __align__(16) __half g_medh[(size_t)B_ * C_ * HW_];     // median result, fp16 NCHW
__device__ float2 g_part2[C_ * 1024];                              // per-CTA channel partials
__device__ float2 g_sb[C_];

// ---------------- PTX helpers (sm_80-era: safe for compute_103) ----------------
__device__ __forceinline__ uint32_t smem_u32(const void* p) {
    uint32_t a;
    asm("{ .reg .u64 t; cvta.to.shared.u64 t, %1; cvt.u32.u64 %0, t; }" : "=r"(a) : "l"(p));
    return a;
}
__device__ __forceinline__ void ldsm4(uint32_t* r, uint32_t addr) {
    asm volatile("ldmatrix.sync.aligned.m8n8.x4.shared.b16 {%0,%1,%2,%3}, [%4];"
        : "=r"(r[0]), "=r"(r[1]), "=r"(r[2]), "=r"(r[3]) : "r"(addr));
}
__device__ __forceinline__ void mma16816(float* d, const uint32_t* a, const uint32_t* b) {
    asm volatile("mma.sync.aligned.m16n8k16.row.col.f32.f16.f16.f32 "
        "{%0,%1,%2,%3}, {%4,%5,%6,%7}, {%8,%9}, {%0,%1,%2,%3};"
        : "+f"(d[0]), "+f"(d[1]), "+f"(d[2]), "+f"(d[3])
        : "r"(a[0]), "r"(a[1]), "r"(a[2]), "r"(a[3]), "r"(b[0]), "r"(b[1]));
}

// SMEM layout (halves): sB halo [132][72] then sA [3][96][72]
#define SB_HALVES (132 * 72)   // 9504 halves = 19008 B
#define TILE_A    (96 * 72)    // 6912 halves = 13824 B
#define DSM_HALVES (SB_HALVES + 3 * TILE_A)   // 30240 halves = 60480 B
// epilogue reuse: yt[96][132] f32 = 50688 B, then sred[128][4] float2 = 4096 B

// ---------------- 1) one-hot indices from hs ----------------
__global__ void idx_kernel(const float* __restrict__ hs) {
    int t = blockIdx.x * blockDim.x + threadIdx.x;
    if (t >= 3 * C_) return;
    int j = t >> 7, c = t & 127;
    int d = 0;
    for (int dd = 0; dd < 32; ++dd)
        if (hs[(j * 32 + dd) * C_ + c] > 0.5f) d = dd;
    g_idx[t] = d;
}

// ---------------- 2) sketched weights -> fp16, [co][tap*128+ci] ----------------
__global__ void wsk_kernel(const float* __restrict__ w2, const float* __restrict__ ss) {
    int e = blockIdx.x * 256 + threadIdx.x;
    if (e >= CO_ * KTOT) return;
    int ci = e & 127, tap = (e >> 7) % 9, co = e / KTOT;
    int j = co >> 5, d = co & 31;
    float sum = 0.f;
    for (int c = 0; c < C_; ++c) {
        int   ic = g_idx[j * C_ + c];
        float wv = w2[(c * C_ + ci) * 9 + tap];
        sum += (ic == d) ? ss[j * C_ + c] * wv : 0.f;
    }
    g_w[e] = __float2half_rn(sum);
}

// ---------------- 3) NCHW fp32 -> padded NHWC fp16 (+ border zeroing) ----------------
__global__ __launch_bounds__(256) void xT_kernel(const float* __restrict__ x) {
    __shared__ float sm[128 * 65];
    const int t = threadIdx.x, h = blockIdx.x, b = blockIdx.y;

    // zero column borders of this block's padded row (hp = h+1)
    if (t < 32) {
        int w = (t & 16) ? 65 : 0;
        int v = t & 15;
        size_t off = (((size_t)b * HP_ + h + 1) * WP_ + w) * C_ + v * 8;
        *(uint4*)(g_xp + off) = make_uint4(0, 0, 0, 0);
    }
    // zero full padded rows 0 / 65
    if (h == 0 || h == 63) {
        int hz = (h == 0) ? 0 : 65;
        for (int g = t; g < 66 * 16; g += 256) {
            int w = g >> 4, v = g & 15;
            size_t off = (((size_t)b * HP_ + hz) * WP_ + w) * C_ + v * 8;
            *(uint4*)(g_xp + off) = make_uint4(0, 0, 0, 0);
        }
    }

    const float* xp = x + (size_t)b * C_ * HW_ + h * W_;
#pragma unroll
    for (int k = 0; k < 32; ++k) {
        int idx = (k << 8) + t;
        int c = idx >> 6, w = idx & 63;
        sm[c * 65 + w] = xp[(size_t)c * HW_ + w];
    }
    __syncthreads();
    size_t dbase = (((size_t)b * HP_ + h + 1) * WP_ + 1) * C_;
#pragma unroll
    for (int k = 0; k < 16; ++k) {
        int idx = (k << 8) + t;
        int w = idx >> 6, c2 = idx & 63;
        float f0 = sm[(2 * c2) * 65 + w];
        float f1 = sm[(2 * c2 + 1) * 65 + w];
        __half2 hh = __floats2half2_rn(f0, f1);
        size_t o = dbase + (size_t)w * C_ + 2 * c2;
        *(unsigned*)(g_xp + o) = *(unsigned*)&hh;
    }
}

// ---------------- 4) mma.sync conv (R12 form) + fused BN partial sums ----------------
__global__ __launch_bounds__(256, 2)
void conv_mma_kernel(const float* __restrict__ ss) {
    extern __shared__ __half dsm[];
    __half* sB = dsm;                  // halo: 132 pixel-rows x 72 (64 used)
    __half* sA = dsm + SB_HALVES;      // 3 kw tiles x 96 rows x 72

    const int tid = threadIdx.x, warp = tid >> 5, lane = tid & 31;
    const int b = blockIdx.y, h0 = blockIdx.x << 1;   // 2 output rows per CTA
    const int m0 = (warp >> 2) * 48;                  // 2 warps in M: 48 rows each
    const int n0 = (warp & 3) * 32;                   // 4 warps in N: 32 pixels each

    const uint32_t aB = smem_u32(sB), aA = smem_u32(sA);

    // ldmatrix per-lane offsets
    uint32_t a_off[3];
#pragma unroll
    for (int ti = 0; ti < 3; ++ti)
        a_off[ti] = (uint32_t)((m0 + ti * 16 + (lane & 15)) * 144 + (lane >> 4) * 16);
    uint32_t b_off[2];
    {
        int o = lane >> 3;
#pragma unroll
        for (int u = 0; u < 2; ++u) {
            int pix  = n0 + u * 16 + (o >> 1) * 8 + (lane & 7);
            int hrow = (pix >> 6) * 66 + (pix & 63);       // halo row (2 x 66 layout)
            b_off[u] = (uint32_t)(hrow * 144 + (o & 1) * 16);
        }
    }

    float acc[3][4][4];
#pragma unroll
    for (int ti = 0; ti < 3; ++ti)
#pragma unroll
        for (int tj = 0; tj < 4; ++tj)
#pragma unroll
            for (int v = 0; v < 4; ++v) acc[ti][tj][v] = 0.f;

#pragma unroll 1
    for (int it = 0; it < 6; ++it) {
        const int kh = it >> 1, half = it & 1;
        __syncthreads();
        // stage B halo: 132 rows (2 x 66 cols) x 64 ci = 1056 uint4
        const __half* xb = g_xp + (((size_t)b * HP_ + h0 + kh) * WP_) * C_ + half * 64;
#pragma unroll
        for (int k = 0; k < 5; ++k) {
            int g = tid + (k << 8);
            if (g < 1056) {
                int row = g >> 3, sub = g & 7;
                int r = (row >= 66) ? 1 : 0;
                int wn = row - r * 66;
                *(uint4*)(sB + row * 72 + sub * 8) =
                    *(const uint4*)(xb + ((size_t)r * WP_ + wn) * C_ + sub * 8);
            }
        }
        // stage A: 3 kw tiles, 96 rows x 64 ci each = 2304 uint4 (9 per thread)
        const __half* wb = g_w + (kh * 3) * 128 + half * 64;
#pragma unroll
        for (int k = 0; k < 9; ++k) {
            int g = tid + (k << 8);
            int tl = g / 768, rem = g - tl * 768;
            int row = rem >> 3, sub = rem & 7;
            *(uint4*)(sA + tl * TILE_A + row * 72 + sub * 8) =
                *(const uint4*)(wb + (size_t)row * KTOT + tl * 128 + sub * 8);
        }
        __syncthreads();

#pragma unroll
        for (int kw = 0; kw < 3; ++kw) {
#pragma unroll
            for (int s = 0; s < 4; ++s) {
                uint32_t a[3][4], bb2[8];
#pragma unroll
                for (int ti = 0; ti < 3; ++ti)
                    ldsm4(a[ti], aA + kw * 13824 + a_off[ti] + s * 32);
#pragma unroll
                for (int u = 0; u < 2; ++u)
                    ldsm4(&bb2[u * 4], aB + b_off[u] + kw * 144 + s * 32);
#pragma unroll
                for (int ti = 0; ti < 3; ++ti)
#pragma unroll
                    for (int tj = 0; tj < 4; ++tj)
                        mma16816(acc[ti][tj], a[ti], &bb2[tj * 2]);
            }
        }
    }

    // ---- accumulators -> SMEM yt[96][132] (reuse staging smem) ----
    __syncthreads();
    float* yt = (float*)dsm;
    float2* sred = (float2*)((char*)dsm + 50688);    // [128 channels][4 warps]
#pragma unroll
    for (int ti = 0; ti < 3; ++ti)
#pragma unroll
        for (int tj = 0; tj < 4; ++tj) {
            int row = m0 + ti * 16 + (lane >> 2);
            int col = n0 + tj * 8 + (lane & 3) * 2;
            *(float2*)&yt[row * 132 + col]       = make_float2(acc[ti][tj][0], acc[ti][tj][1]);
            *(float2*)&yt[(row + 8) * 132 + col] = make_float2(acc[ti][tj][2], acc[ti][tj][3]);
        }
    __syncthreads();

    // ---- unsketch + median-of-3 + fp16 store + fused per-channel partial sums ----
    const int sp = tid & 127, cg = tid >> 7;
    const int hh = h0 + (sp >> 6), wn = sp & 63;
    __half* mbase = g_medh + ((size_t)b * C_) * HW_ + hh * W_ + wn;
#pragma unroll 1
    for (int cc = 0; cc < 64; ++cc) {
        int c = (cg << 6) + cc;
        int i0 = g_idx[c], i1 = g_idx[C_ + c], i2 = g_idx[2 * C_ + c];
        float s0 = ss[c], s1 = ss[C_ + c], s2 = ss[2 * C_ + c];
        float v0 = s0 * yt[i0 * 132 + sp];
        float v1 = s1 * yt[(32 + i1) * 132 + sp];
        float v2 = s2 * yt[(64 + i2) * 132 + sp];
        float mx = fmaxf(v0, v1), mn = fminf(v0, v1);
        float m  = fmaxf(mn, fminf(mx, v2));
        mbase[(size_t)c * HW_] = __float2half_rn(m);
        // warp-tree partial (fills STG latency slots)
        float sacc = m, qacc = m * m;
#pragma unroll
        for (int o = 16; o; o >>= 1) {
            sacc += __shfl_down_sync(0xffffffffu, sacc, o);
            qacc += __shfl_down_sync(0xffffffffu, qacc, o);
        }
        if (lane == 0) sred[c * 4 + (warp & 3)] = make_float2(sacc, qacc);
    }
    __syncthreads();
    if (tid < 128) {
        float2 p0 = sred[tid * 4 + 0], p1 = sred[tid * 4 + 1];
        float2 p2 = sred[tid * 4 + 2], p3 = sred[tid * 4 + 3];
        g_part2[(tid << 10) + (blockIdx.y << 5) + blockIdx.x] =
            make_float2(p0.x + p1.x + p2.x + p3.x, p0.y + p1.y + p2.y + p3.y);
    }
}

// ---------------- 5) reduce partials -> (scale, bias) ----------------
__global__ void stats_kernel(const float* __restrict__ gamma2,
                             const float* __restrict__ beta2) {
    const int c = blockIdx.x, tid = threadIdx.x;
    float S = 0.f, Q = 0.f;
    for (int i = tid; i < 1024; i += 256) {
        float2 p = g_part2[(c << 10) + i];
        S += p.x; Q += p.y;
    }
    __shared__ float rs[8], rq[8];
#pragma unroll
    for (int o = 16; o; o >>= 1) {
        S += __shfl_down_sync(0xffffffffu, S, o);
        Q += __shfl_down_sync(0xffffffffu, Q, o);
    }
    if ((tid & 31) == 0) { rs[tid >> 5] = S; rq[tid >> 5] = Q; }
    __syncthreads();
    if (tid == 0) {
        float Ss = 0.f, Qq = 0.f;
        for (int i = 0; i < 8; ++i) { Ss += rs[i]; Qq += rq[i]; }
        const float invn = 1.f / (float)(B_ * HW_);
        float mean  = Ss * invn;
        float var   = Qq * invn - mean * mean;
        float scale = gamma2[c] * rsqrtf(var + 1e-5f);
        g_sb[c] = make_float2(scale, beta2[c] - mean * scale);
    }
}

// ---------------- 6) normalize + ReLU + residual ----------------
__global__ void out_kernel(const float* __restrict__ x, float* __restrict__ out) {
    size_t i = ((size_t)blockIdx.x * 256 + threadIdx.x) << 2;
    int c = (int)((i >> 12) & 127);
    float2 sb = g_sb[c];
    uint2 mh = *(const uint2*)&g_medh[i];
    float2 f01 = __half22float2(*(const __half2*)&mh.x);
    float2 f23 = __half22float2(*(const __half2*)&mh.y);
    float4 xv = *(const float4*)&x[i];
    float4 o;
    o.x = fmaxf(fmaf(f01.x, sb.x, sb.y), 0.f) + xv.x;
    o.y = fmaxf(fmaf(f01.y, sb.x, sb.y), 0.f) + xv.y;
    o.z = fmaxf(fmaf(f23.x, sb.x, sb.y), 0.f) + xv.z;
    o.w = fmaxf(fmaf(f23.y, sb.x, sb.y), 0.f) + xv.w;
    *(float4*)&out[i] = o;
}

// ---------------- launch ----------------
extern "C" void kernel_launch(void* const* d_in, const int* in_sizes, int n_in,
                              void* d_out, int out_size) {
    (void)in_sizes; (void)n_in; (void)out_size;
    const float* x      = (const float*)d_in[0];
    // d_in[1] = w1, d_in[3] = gamma1, d_in[4] = beta1: unused (reference discards out1)
    const float* w2     = (const float*)d_in[2];
    const float* gamma2 = (const float*)d_in[5];
    const float* beta2  = (const float*)d_in[6];
    const float* hs     = (const float*)d_in[7];
    const float* ss     = (const float*)d_in[8];
    float* out = (float*)d_out;

    const int DSMEM = DSM_HALVES * 2;   // 60480 B (yt 50688 + sred 4096 fit)
    cudaFuncSetAttribute(conv_mma_kernel, cudaFuncAttributeMaxDynamicSharedMemorySize, DSMEM);

    idx_kernel<<<2, 256>>>(hs);
    wsk_kernel<<<(CO_ * KTOT + 255) / 256, 256>>>(w2, ss);
    xT_kernel<<<dim3(H_, B_), 256>>>(x);
    conv_mma_kernel<<<dim3(H_ / 2, B_), 256, DSMEM>>>(ss);
    stats_kernel<<<C_, 256>>>(gamma2, beta2);
    out_kernel<<<(B_ * C_ * HW_) / 1024, 256>>>(x, out);
}

// round 16
// speedup vs baseline: 1.0285x; 1.0219x over previous
#include <cuda_runtime.h>
#include <cuda_fp16.h>
#include <cstdint>

#define B_   32
#define C_   128
#define CO_  96
#define H_   64
#define W_   64
#define HW_  4096
#define HP_  66
#define WP_  66
#define KTOT 1152   // 9 taps * 128 ci

// ---------------- device scratch (no allocations allowed) ----------------
__device__ __align__(16) __half g_xp[(size_t)B_ * HP_ * WP_ * C_]; // padded NHWC fp16
__device__ __align__(16) __half g_w[CO_ * KTOT];                   // A: [co][tap*128+ci]
__device__ int    g_idx[3 * C_];
__device__ __align__(16) __half g_medh[(size_t)B_ * C_ * HW_];     // median result, fp16 NCHW
__device__ float2 g_part[C_ * 8];
__device__ float2 g_sb[C_];

// ---------------- PTX helpers (sm_80-era: safe for compute_103) ----------------
__device__ __forceinline__ uint32_t smem_u32(const void* p) {
    uint32_t a;
    asm("{ .reg .u64 t; cvta.to.shared.u64 t, %1; cvt.u32.u64 %0, t; }" : "=r"(a) : "l"(p));
    return a;
}
__device__ __forceinline__ void ldsm4(uint32_t* r, uint32_t addr) {
    asm volatile("ldmatrix.sync.aligned.m8n8.x4.shared.b16 {%0,%1,%2,%3}, [%4];"
        : "=r"(r[0]), "=r"(r[1]), "=r"(r[2]), "=r"(r[3]) : "r"(addr));
}
__device__ __forceinline__ void mma16816(float* d, const uint32_t* a, const uint32_t* b) {
    asm volatile("mma.sync.aligned.m16n8k16.row.col.f32.f16.f16.f32 "
        "{%0,%1,%2,%3}, {%4,%5,%6,%7}, {%8,%9}, {%0,%1,%2,%3};"
        : "+f"(d[0]), "+f"(d[1]), "+f"(d[2]), "+f"(d[3])
        : "r"(a[0]), "r"(a[1]), "r"(a[2]), "r"(a[3]), "r"(b[0]), "r"(b[1]));
}

// SMEM layout (halves): sB halo [132][72] then sA [3][96][72]
#define SB_HALVES (132 * 72)   // 9504 halves = 19008 B
#define TILE_A    (96 * 72)    // 6912 halves = 13824 B
#define DSM_HALVES (SB_HALVES + 3 * TILE_A)   // 30240 halves = 60480 B
// epilogue reuse: yt[96][132] f32 = 50688 B

// ---------------- 1) one-hot indices from hs ----------------
__global__ void idx_kernel(const float* __restrict__ hs) {
    int t = blockIdx.x * blockDim.x + threadIdx.x;
    if (t >= 3 * C_) return;
    int j = t >> 7, c = t & 127;
    int d = 0;
    for (int dd = 0; dd < 32; ++dd)
        if (hs[(j * 32 + dd) * C_ + c] > 0.5f) d = dd;
    g_idx[t] = d;
}

// ---------------- 2) sketched weights -> fp16, [co][tap*128+ci] ----------------
__global__ void wsk_kernel(const float* __restrict__ w2, const float* __restrict__ ss) {
    int e = blockIdx.x * 256 + threadIdx.x;
    if (e >= CO_ * KTOT) return;
    int ci = e & 127, tap = (e >> 7) % 9, co = e / KTOT;
    int j = co >> 5, d = co & 31;
    float sum = 0.f;
    for (int c = 0; c < C_; ++c) {
        int   ic = g_idx[j * C_ + c];
        float wv = w2[(c * C_ + ci) * 9 + tap];
        sum += (ic == d) ? ss[j * C_ + c] * wv : 0.f;
    }
    g_w[e] = __float2half_rn(sum);
}

// ---------------- 3) NCHW fp32 -> padded NHWC fp16 (+ fused border zeroing) ----------------
__global__ __launch_bounds__(256) void xT_kernel(const float* __restrict__ x) {
    __shared__ float sm[128 * 65];
    const int t = threadIdx.x, h = blockIdx.x, b = blockIdx.y;

    // zero column borders of this block's padded row (hp = h+1)
    if (t < 32) {
        int w = (t & 16) ? 65 : 0;
        int v = t & 15;
        size_t off = (((size_t)b * HP_ + h + 1) * WP_ + w) * C_ + v * 8;
        *(uint4*)(g_xp + off) = make_uint4(0, 0, 0, 0);
    }
    // zero full padded rows 0 / 65
    if (h == 0 || h == 63) {
        int hz = (h == 0) ? 0 : 65;
        for (int g = t; g < 66 * 16; g += 256) {
            int w = g >> 4, v = g & 15;
            size_t off = (((size_t)b * HP_ + hz) * WP_ + w) * C_ + v * 8;
            *(uint4*)(g_xp + off) = make_uint4(0, 0, 0, 0);
        }
    }

    const float* xp = x + (size_t)b * C_ * HW_ + h * W_;
#pragma unroll
    for (int k = 0; k < 32; ++k) {
        int idx = (k << 8) + t;
        int c = idx >> 6, w = idx & 63;
        sm[c * 65 + w] = xp[(size_t)c * HW_ + w];
    }
    __syncthreads();
    size_t dbase = (((size_t)b * HP_ + h + 1) * WP_ + 1) * C_;
#pragma unroll
    for (int k = 0; k < 16; ++k) {
        int idx = (k << 8) + t;
        int w = idx >> 6, c2 = idx & 63;
        float f0 = sm[(2 * c2) * 65 + w];
        float f1 = sm[(2 * c2 + 1) * 65 + w];
        __half2 hh = __floats2half2_rn(f0, f1);
        size_t o = dbase + (size_t)w * C_ + 2 * c2;
        *(unsigned*)(g_xp + o) = *(unsigned*)&hh;
    }
}

// ---------------- 4) mma.sync conv: 128 thr, 4 warps of M48 x N64 ----------------
__global__ __launch_bounds__(128, 2)
void conv_mma_kernel(const float* __restrict__ ss) {
    extern __shared__ __half dsm[];
    __half* sB = dsm;                  // halo: 132 pixel-rows x 72 (64 used)
    __half* sA = dsm + SB_HALVES;      // 3 kw tiles x 96 rows x 72

    const int tid = threadIdx.x, warp = tid >> 5, lane = tid & 31;
    const int b = blockIdx.y, h0 = blockIdx.x << 1;   // 2 output rows per CTA
    const int m0 = (warp >> 1) * 48;                  // 2 warps in M: 48 rows each
    const int n0 = (warp & 1) * 64;                   // 2 warps in N: 64 pixels each

    const uint32_t aB = smem_u32(sB), aA = smem_u32(sA);

    // ldmatrix per-lane offsets
    uint32_t a_off[3];
#pragma unroll
    for (int ti = 0; ti < 3; ++ti)
        a_off[ti] = (uint32_t)((m0 + ti * 16 + (lane & 15)) * 144 + (lane >> 4) * 16);
    uint32_t b_off[4];
    {
        int o = lane >> 3;
#pragma unroll
        for (int u = 0; u < 4; ++u) {
            int pix  = n0 + u * 16 + (o >> 1) * 8 + (lane & 7);
            int hrow = (pix >> 6) * 66 + (pix & 63);       // halo row (2 x 66 layout)
            b_off[u] = (uint32_t)(hrow * 144 + (o & 1) * 16);
        }
    }

    float acc[3][8][4];
#pragma unroll
    for (int ti = 0; ti < 3; ++ti)
#pragma unroll
        for (int tj = 0; tj < 8; ++tj)
#pragma unroll
            for (int v = 0; v < 4; ++v) acc[ti][tj][v] = 0.f;

#pragma unroll 1
    for (int it = 0; it < 6; ++it) {
        const int kh = it >> 1, half = it & 1;
        __syncthreads();
        // stage B halo: 132 rows (2 x 66 cols) x 64 ci = 1056 uint4
        const __half* xb = g_xp + (((size_t)b * HP_ + h0 + kh) * WP_) * C_ + half * 64;
#pragma unroll
        for (int k = 0; k < 9; ++k) {
            int g = tid + (k << 7);
            if (g < 1056) {
                int row = g >> 3, sub = g & 7;
                int r = (row >= 66) ? 1 : 0;
                int wn = row - r * 66;
                *(uint4*)(sB + row * 72 + sub * 8) =
                    *(const uint4*)(xb + ((size_t)r * WP_ + wn) * C_ + sub * 8);
            }
        }
        // stage A: 3 kw tiles, 96 rows x 64 ci each = 2304 uint4 (18 per thread)
        const __half* wb = g_w + (kh * 3) * 128 + half * 64;
#pragma unroll
        for (int k = 0; k < 18; ++k) {
            int g = tid + (k << 7);
            int tl = g / 768, rem = g - tl * 768;
            int row = rem >> 3, sub = rem & 7;
            *(uint4*)(sA + tl * TILE_A + row * 72 + sub * 8) =
                *(const uint4*)(wb + (size_t)row * KTOT + tl * 128 + sub * 8);
        }
        __syncthreads();

#pragma unroll
        for (int kw = 0; kw < 3; ++kw) {
#pragma unroll
            for (int s = 0; s < 4; ++s) {
                uint32_t a[3][4], bb2[16];
#pragma unroll
                for (int ti = 0; ti < 3; ++ti)
                    ldsm4(a[ti], aA + kw * 13824 + a_off[ti] + s * 32);
#pragma unroll
                for (int u = 0; u < 4; ++u)
                    ldsm4(&bb2[u * 4], aB + b_off[u] + kw * 144 + s * 32);
#pragma unroll
                for (int ti = 0; ti < 3; ++ti)
#pragma unroll
                    for (int tj = 0; tj < 8; ++tj)
                        mma16816(acc[ti][tj], a[ti], &bb2[tj * 2]);
            }
        }
    }

    // ---- accumulators -> SMEM yt[96][132] (reuse staging smem) ----
    __syncthreads();
    float* yt = (float*)dsm;
#pragma unroll
    for (int ti = 0; ti < 3; ++ti)
#pragma unroll
        for (int tj = 0; tj < 8; ++tj) {
            int row = m0 + ti * 16 + (lane >> 2);
            int col = n0 + tj * 8 + (lane & 3) * 2;
            *(float2*)&yt[row * 132 + col]       = make_float2(acc[ti][tj][0], acc[ti][tj][1]);
            *(float2*)&yt[(row + 8) * 132 + col] = make_float2(acc[ti][tj][2], acc[ti][tj][3]);
        }
    __syncthreads();

    // ---- unsketch (gather + sign) + median-of-3, fp16 coalesced store ----
    const int sp = tid;                 // 128 pixels, one per thread
    const int hh = h0 + (sp >> 6), wn = sp & 63;
    __half* mbase = g_medh + ((size_t)b * C_) * HW_ + hh * W_ + wn;
#pragma unroll 1
    for (int c = 0; c < C_; ++c) {
        int i0 = g_idx[c], i1 = g_idx[C_ + c], i2 = g_idx[2 * C_ + c];
        float s0 = ss[c], s1 = ss[C_ + c], s2 = ss[2 * C_ + c];
        float v0 = s0 * yt[i0 * 132 + sp];
        float v1 = s1 * yt[(32 + i1) * 132 + sp];
        float v2 = s2 * yt[(64 + i2) * 132 + sp];
        float mx = fmaxf(v0, v1), mn = fminf(v0, v1);
        mbase[(size_t)c * HW_] = __float2half_rn(fmaxf(mn, fminf(mx, v2)));
    }
}

// ---------------- 5) BN stats (fp16 med), two-stage ----------------
__global__ void stats1_kernel() {
    const int c = blockIdx.x, q = blockIdx.y, tid = threadIdx.x;
    float s = 0.f, qq = 0.f;
    for (int bb = q * 4; bb < q * 4 + 4; ++bb) {
        const uint4* p = (const uint4*)(g_medh + ((size_t)bb * C_ + c) * HW_);
        for (int i = tid; i < HW_ / 8; i += 256) {
            uint4 v = p[i];
            const uint32_t wrd[4] = {v.x, v.y, v.z, v.w};
#pragma unroll
            for (int u = 0; u < 4; ++u) {
                float2 f = __half22float2(*(const __half2*)&wrd[u]);
                s += f.x + f.y;
                qq = fmaf(f.x, f.x, fmaf(f.y, f.y, qq));
            }
        }
    }
    __shared__ float rs[8], rq[8];
#pragma unroll
    for (int o = 16; o; o >>= 1) {
        s  += __shfl_down_sync(0xffffffffu, s,  o);
        qq += __shfl_down_sync(0xffffffffu, qq, o);
    }
    if ((tid & 31) == 0) { rs[tid >> 5] = s; rq[tid >> 5] = qq; }
    __syncthreads();
    if (tid == 0) {
        float S = 0.f, Q = 0.f;
        for (int i = 0; i < 8; ++i) { S += rs[i]; Q += rq[i]; }
        g_part[c * 8 + q] = make_float2(S, Q);
    }
}
__global__ void stats2_kernel(const float* __restrict__ gamma2,
                              const float* __restrict__ beta2) {
    int c = threadIdx.x;
    float S = 0.f, Q = 0.f;
    for (int q = 0; q < 8; ++q) { float2 p = g_part[c * 8 + q]; S += p.x; Q += p.y; }
    const float invn = 1.f / (float)(B_ * HW_);
    float mean  = S * invn;
    float var   = Q * invn - mean * mean;
    float scale = gamma2[c] * rsqrtf(var + 1e-5f);
    g_sb[c] = make_float2(scale, beta2[c] - mean * scale);
}

// ---------------- 6) normalize + ReLU + residual ----------------
__global__ void out_kernel(const float* __restrict__ x, float* __restrict__ out) {
    size_t i = ((size_t)blockIdx.x * 256 + threadIdx.x) << 2;
    int c = (int)((i >> 12) & 127);
    float2 sb = g_sb[c];
    uint2 mh = *(const uint2*)&g_medh[i];
    float2 f01 = __half22float2(*(const __half2*)&mh.x);
    float2 f23 = __half22float2(*(const __half2*)&mh.y);
    float4 xv = *(const float4*)&x[i];
    float4 o;
    o.x = fmaxf(fmaf(f01.x, sb.x, sb.y), 0.f) + xv.x;
    o.y = fmaxf(fmaf(f01.y, sb.x, sb.y), 0.f) + xv.y;
    o.z = fmaxf(fmaf(f23.x, sb.x, sb.y), 0.f) + xv.z;
    o.w = fmaxf(fmaf(f23.y, sb.x, sb.y), 0.f) + xv.w;
    *(float4*)&out[i] = o;
}

// ---------------- launch ----------------
extern "C" void kernel_launch(void* const* d_in, const int* in_sizes, int n_in,
                              void* d_out, int out_size) {
    (void)in_sizes; (void)n_in; (void)out_size;
    const float* x      = (const float*)d_in[0];
    // d_in[1] = w1, d_in[3] = gamma1, d_in[4] = beta1: unused (reference discards out1)
    const float* w2     = (const float*)d_in[2];
    const float* gamma2 = (const float*)d_in[5];
    const float* beta2  = (const float*)d_in[6];
    const float* hs     = (const float*)d_in[7];
    const float* ss     = (const float*)d_in[8];
    float* out = (float*)d_out;

    const int DSMEM = DSM_HALVES * 2;   // 60480 B (epilogue yt 50688 B fits)
    cudaFuncSetAttribute(conv_mma_kernel, cudaFuncAttributeMaxDynamicSharedMemorySize, DSMEM);

    idx_kernel<<<2, 256>>>(hs);
    wsk_kernel<<<(CO_ * KTOT + 255) / 256, 256>>>(w2, ss);
    xT_kernel<<<dim3(H_, B_), 256>>>(x);
    conv_mma_kernel<<<dim3(H_ / 2, B_), 128, DSMEM>>>(ss);
    stats1_kernel<<<dim3(C_, 8), 256>>>();
    stats2_kernel<<<1, C_>>>(gamma2, beta2);
    out_kernel<<<(B_ * C_ * HW_) / 1024, 256>>>(x, out);
}

// round 17
// speedup vs baseline: 1.0675x; 1.0380x over previous
#include <cuda_runtime.h>
#include <cuda_fp16.h>
#include <cstdint>

#define B_   32
#define C_   128
#define CO_  96
#define H_   64
#define W_   64
#define HW_  4096
#define HP_  66
#define WP_  66
#define KTOT 1152   // 9 taps * 128 ci

// ---------------- device scratch (no allocations allowed) ----------------
__device__ __align__(16) __half g_xp[(size_t)B_ * HP_ * WP_ * C_]; // padded NHWC fp16
__device__ __align__(16) __half g_w[CO_ * KTOT];                   // A: [co][tap*128+ci]
__device__ int    g_idx[3 * C_];
__device__ __align__(16) __half g_medh[(size_t)B_ * C_ * HW_];     // median result, fp16 NCHW
__device__ float2 g_part[C_ * 8];
__device__ float2 g_sb[C_];

// ---------------- PTX helpers (sm_80-era: safe for compute_103) ----------------
__device__ __forceinline__ uint32_t smem_u32(const void* p) {
    uint32_t a;
    asm("{ .reg .u64 t; cvta.to.shared.u64 t, %1; cvt.u32.u64 %0, t; }" : "=r"(a) : "l"(p));
    return a;
}
__device__ __forceinline__ void ldsm4(uint32_t* r, uint32_t addr) {
    asm volatile("ldmatrix.sync.aligned.m8n8.x4.shared.b16 {%0,%1,%2,%3}, [%4];"
        : "=r"(r[0]), "=r"(r[1]), "=r"(r[2]), "=r"(r[3]) : "r"(addr));
}
__device__ __forceinline__ void mma16816(float* d, const uint32_t* a, const uint32_t* b) {
    asm volatile("mma.sync.aligned.m16n8k16.row.col.f32.f16.f16.f32 "
        "{%0,%1,%2,%3}, {%4,%5,%6,%7}, {%8,%9}, {%0,%1,%2,%3};"
        : "+f"(d[0]), "+f"(d[1]), "+f"(d[2]), "+f"(d[3])
        : "r"(a[0]), "r"(a[1]), "r"(a[2]), "r"(a[3]), "r"(b[0]), "r"(b[1]));
}

// SMEM layout (halves): sB halo [132][72] then sA [3][96][72]
#define SB_HALVES (132 * 72)   // 9504 halves = 19008 B
#define TILE_A    (96 * 72)    // 6912 halves = 13824 B
#define DSM_HALVES (SB_HALVES + 3 * TILE_A)   // 30240 halves = 60480 B
// epilogue reuse: yt[96][132] f32 = 50688 B

// ---------------- 1) one-hot indices from hs ----------------
__global__ void idx_kernel(const float* __restrict__ hs) {
    int t = blockIdx.x * blockDim.x + threadIdx.x;
    if (t >= 3 * C_) return;
    int j = t >> 7, c = t & 127;
    int d = 0;
    for (int dd = 0; dd < 32; ++dd)
        if (hs[(j * 32 + dd) * C_ + c] > 0.5f) d = dd;
    g_idx[t] = d;
}

// ---------------- 2) sketched weights -> fp16, [co][tap*128+ci] ----------------
__global__ void wsk_kernel(const float* __restrict__ w2, const float* __restrict__ ss) {
    int e = blockIdx.x * 256 + threadIdx.x;
    if (e >= CO_ * KTOT) return;
    int ci = e & 127, tap = (e >> 7) % 9, co = e / KTOT;
    int j = co >> 5, d = co & 31;
    float sum = 0.f;
    for (int c = 0; c < C_; ++c) {
        int   ic = g_idx[j * C_ + c];
        float wv = w2[(c * C_ + ci) * 9 + tap];
        sum += (ic == d) ? ss[j * C_ + c] * wv : 0.f;
    }
    g_w[e] = __float2half_rn(sum);
}

// ---------------- 3) NCHW fp32 -> padded NHWC fp16 (+ fused border zeroing) ----------------
__global__ __launch_bounds__(256) void xT_kernel(const float* __restrict__ x) {
    __shared__ float sm[128 * 65];
    const int t = threadIdx.x, h = blockIdx.x, b = blockIdx.y;

    // zero column borders of this block's padded row (hp = h+1)
    if (t < 32) {
        int w = (t & 16) ? 65 : 0;
        int v = t & 15;
        size_t off = (((size_t)b * HP_ + h + 1) * WP_ + w) * C_ + v * 8;
        *(uint4*)(g_xp + off) = make_uint4(0, 0, 0, 0);
    }
    // zero full padded rows 0 / 65
    if (h == 0 || h == 63) {
        int hz = (h == 0) ? 0 : 65;
        for (int g = t; g < 66 * 16; g += 256) {
            int w = g >> 4, v = g & 15;
            size_t off = (((size_t)b * HP_ + hz) * WP_ + w) * C_ + v * 8;
            *(uint4*)(g_xp + off) = make_uint4(0, 0, 0, 0);
        }
    }

    const float* xp = x + (size_t)b * C_ * HW_ + h * W_;
#pragma unroll
    for (int k = 0; k < 32; ++k) {
        int idx = (k << 8) + t;
        int c = idx >> 6, w = idx & 63;
        sm[c * 65 + w] = xp[(size_t)c * HW_ + w];
    }
    __syncthreads();
    size_t dbase = (((size_t)b * HP_ + h + 1) * WP_ + 1) * C_;
#pragma unroll
    for (int k = 0; k < 16; ++k) {
        int idx = (k << 8) + t;
        int w = idx >> 6, c2 = idx & 63;
        float f0 = sm[(2 * c2) * 65 + w];
        float f1 = sm[(2 * c2 + 1) * 65 + w];
        __half2 hh = __floats2half2_rn(f0, f1);
        size_t o = dbase + (size_t)w * C_ + 2 * c2;
        *(unsigned*)(g_xp + o) = *(unsigned*)&hh;
    }
}

// ---------------- 4) mma.sync conv: 128 thr, 4 warps of M48 x N64, 3 CTAs/SM ----------------
__global__ __launch_bounds__(128, 3)
void conv_mma_kernel(const float* __restrict__ ss) {
    extern __shared__ __half dsm[];
    __half* sB = dsm;                  // halo: 132 pixel-rows x 72 (64 used)
    __half* sA = dsm + SB_HALVES;      // 3 kw tiles x 96 rows x 72

    const int tid = threadIdx.x, warp = tid >> 5, lane = tid & 31;
    const int b = blockIdx.y, h0 = blockIdx.x << 1;   // 2 output rows per CTA
    const int m0 = (warp >> 1) * 48;                  // 2 warps in M: 48 rows each
    const int n0 = (warp & 1) * 64;                   // 2 warps in N: 64 pixels each

    const uint32_t aB = smem_u32(sB), aA = smem_u32(sA);

    // ldmatrix per-lane offsets
    uint32_t a_off[3];
#pragma unroll
    for (int ti = 0; ti < 3; ++ti)
        a_off[ti] = (uint32_t)((m0 + ti * 16 + (lane & 15)) * 144 + (lane >> 4) * 16);
    uint32_t b_off[4];
    {
        int o = lane >> 3;
#pragma unroll
        for (int u = 0; u < 4; ++u) {
            int pix  = n0 + u * 16 + (o >> 1) * 8 + (lane & 7);
            int hrow = (pix >> 6) * 66 + (pix & 63);       // halo row (2 x 66 layout)
            b_off[u] = (uint32_t)(hrow * 144 + (o & 1) * 16);
        }
    }

    float acc[3][8][4];
#pragma unroll
    for (int ti = 0; ti < 3; ++ti)
#pragma unroll
        for (int tj = 0; tj < 8; ++tj)
#pragma unroll
            for (int v = 0; v < 4; ++v) acc[ti][tj][v] = 0.f;

#pragma unroll 1
    for (int it = 0; it < 6; ++it) {
        const int kh = it >> 1, half = it & 1;
        __syncthreads();
        // stage B halo: 132 rows (2 x 66 cols) x 64 ci = 1056 uint4
        const __half* xb = g_xp + (((size_t)b * HP_ + h0 + kh) * WP_) * C_ + half * 64;
#pragma unroll
        for (int k = 0; k < 9; ++k) {
            int g = tid + (k << 7);
            if (g < 1056) {
                int row = g >> 3, sub = g & 7;
                int r = (row >= 66) ? 1 : 0;
                int wn = row - r * 66;
                *(uint4*)(sB + row * 72 + sub * 8) =
                    *(const uint4*)(xb + ((size_t)r * WP_ + wn) * C_ + sub * 8);
            }
        }
        // stage A: 3 kw tiles, 96 rows x 64 ci each = 2304 uint4 (18 per thread)
        const __half* wb = g_w + (kh * 3) * 128 + half * 64;
#pragma unroll
        for (int k = 0; k < 18; ++k) {
            int g = tid + (k << 7);
            int tl = g / 768, rem = g - tl * 768;
            int row = rem >> 3, sub = rem & 7;
            *(uint4*)(sA + tl * TILE_A + row * 72 + sub * 8) =
                *(const uint4*)(wb + (size_t)row * KTOT + tl * 128 + sub * 8);
        }
        __syncthreads();

#pragma unroll
        for (int kw = 0; kw < 3; ++kw) {
#pragma unroll
            for (int s = 0; s < 4; ++s) {
                uint32_t a[3][4];
#pragma unroll
                for (int ti = 0; ti < 3; ++ti)
                    ldsm4(a[ti], aA + kw * 13824 + a_off[ti] + s * 32);
                // consume B fragments immediately to keep register pressure low
#pragma unroll
                for (int u = 0; u < 4; ++u) {
                    uint32_t bb[4];
                    ldsm4(bb, aB + b_off[u] + kw * 144 + s * 32);
#pragma unroll
                    for (int ti = 0; ti < 3; ++ti) {
                        mma16816(acc[ti][2 * u],     a[ti], &bb[0]);
                        mma16816(acc[ti][2 * u + 1], a[ti], &bb[2]);
                    }
                }
            }
        }
    }

    // ---- accumulators -> SMEM yt[96][132] (reuse staging smem) ----
    __syncthreads();
    float* yt = (float*)dsm;
#pragma unroll
    for (int ti = 0; ti < 3; ++ti)
#pragma unroll
        for (int tj = 0; tj < 8; ++tj) {
            int row = m0 + ti * 16 + (lane >> 2);
            int col = n0 + tj * 8 + (lane & 3) * 2;
            *(float2*)&yt[row * 132 + col]       = make_float2(acc[ti][tj][0], acc[ti][tj][1]);
            *(float2*)&yt[(row + 8) * 132 + col] = make_float2(acc[ti][tj][2], acc[ti][tj][3]);
        }
    __syncthreads();

    // ---- unsketch (gather + sign) + median-of-3, fp16 coalesced store ----
    const int sp = tid;                 // 128 pixels, one per thread
    const int hh = h0 + (sp >> 6), wn = sp & 63;
    __half* mbase = g_medh + ((size_t)b * C_) * HW_ + hh * W_ + wn;
#pragma unroll 1
    for (int c = 0; c < C_; ++c) {
        int i0 = g_idx[c], i1 = g_idx[C_ + c], i2 = g_idx[2 * C_ + c];
        float s0 = ss[c], s1 = ss[C_ + c], s2 = ss[2 * C_ + c];
        float v0 = s0 * yt[i0 * 132 + sp];
        float v1 = s1 * yt[(32 + i1) * 132 + sp];
        float v2 = s2 * yt[(64 + i2) * 132 + sp];
        float mx = fmaxf(v0, v1), mn = fminf(v0, v1);
        mbase[(size_t)c * HW_] = __float2half_rn(fmaxf(mn, fminf(mx, v2)));
    }
}

// ---------------- 5) BN stats (fp16 med), two-stage ----------------
__global__ void stats1_kernel() {
    const int c = blockIdx.x, q = blockIdx.y, tid = threadIdx.x;
    float s = 0.f, qq = 0.f;
    for (int bb = q * 4; bb < q * 4 + 4; ++bb) {
        const uint4* p = (const uint4*)(g_medh + ((size_t)bb * C_ + c) * HW_);
        for (int i = tid; i < HW_ / 8; i += 256) {
            uint4 v = p[i];
            const uint32_t wrd[4] = {v.x, v.y, v.z, v.w};
#pragma unroll
            for (int u = 0; u < 4; ++u) {
                float2 f = __half22float2(*(const __half2*)&wrd[u]);
                s += f.x + f.y;
                qq = fmaf(f.x, f.x, fmaf(f.y, f.y, qq));
            }
        }
    }
    __shared__ float rs[8], rq[8];
#pragma unroll
    for (int o = 16; o; o >>= 1) {
        s  += __shfl_down_sync(0xffffffffu, s,  o);
        qq += __shfl_down_sync(0xffffffffu, qq, o);
    }
    if ((tid & 31) == 0) { rs[tid >> 5] = s; rq[tid >> 5] = qq; }
    __syncthreads();
    if (tid == 0) {
        float S = 0.f, Q = 0.f;
        for (int i = 0; i < 8; ++i) { S += rs[i]; Q += rq[i]; }
        g_part[c * 8 + q] = make_float2(S, Q);
    }
}
__global__ void stats2_kernel(const float* __restrict__ gamma2,
                              const float* __restrict__ beta2) {
    int c = threadIdx.x;
    float S = 0.f, Q = 0.f;
    for (int q = 0; q < 8; ++q) { float2 p = g_part[c * 8 + q]; S += p.x; Q += p.y; }
    const float invn = 1.f / (float)(B_ * HW_);
    float mean  = S * invn;
    float var   = Q * invn - mean * mean;
    float scale = gamma2[c] * rsqrtf(var + 1e-5f);
    g_sb[c] = make_float2(scale, beta2[c] - mean * scale);
}

// ---------------- 6) normalize + ReLU + residual ----------------
__global__ void out_kernel(const float* __restrict__ x, float* __restrict__ out) {
    size_t i = ((size_t)blockIdx.x * 256 + threadIdx.x) << 2;
    int c = (int)((i >> 12) & 127);
    float2 sb = g_sb[c];
    uint2 mh = *(const uint2*)&g_medh[i];
    float2 f01 = __half22float2(*(const __half2*)&mh.x);
    float2 f23 = __half22float2(*(const __half2*)&mh.y);
    float4 xv = *(const float4*)&x[i];
    float4 o;
    o.x = fmaxf(fmaf(f01.x, sb.x, sb.y), 0.f) + xv.x;
    o.y = fmaxf(fmaf(f01.y, sb.x, sb.y), 0.f) + xv.y;
    o.z = fmaxf(fmaf(f23.x, sb.x, sb.y), 0.f) + xv.z;
    o.w = fmaxf(fmaf(f23.y, sb.x, sb.y), 0.f) + xv.w;
    *(float4*)&out[i] = o;
}

// ---------------- launch ----------------
extern "C" void kernel_launch(void* const* d_in, const int* in_sizes, int n_in,
                              void* d_out, int out_size) {
    (void)in_sizes; (void)n_in; (void)out_size;
    const float* x      = (const float*)d_in[0];
    // d_in[1] = w1, d_in[3] = gamma1, d_in[4] = beta1: unused (reference discards out1)
    const float* w2     = (const float*)d_in[2];
    const float* gamma2 = (const float*)d_in[5];
    const float* beta2  = (const float*)d_in[6];
    const float* hs     = (const float*)d_in[7];
    const float* ss     = (const float*)d_in[8];
    float* out = (float*)d_out;

    const int DSMEM = DSM_HALVES * 2;   // 60480 B (epilogue yt 50688 B fits)
    cudaFuncSetAttribute(conv_mma_kernel, cudaFuncAttributeMaxDynamicSharedMemorySize, DSMEM);

    idx_kernel<<<2, 256>>>(hs);
    wsk_kernel<<<(CO_ * KTOT + 255) / 256, 256>>>(w2, ss);
    xT_kernel<<<dim3(H_, B_), 256>>>(x);
    conv_mma_kernel<<<dim3(H_ / 2, B_), 128, DSMEM>>>(ss);
    stats1_kernel<<<dim3(C_, 8), 256>>>();
    stats2_kernel<<<1, C_>>>(gamma2, beta2);
    out_kernel<<<(B_ * C_ * HW_) / 1024, 256>>>(x, out);
}